// round 2
// baseline (speedup 1.0000x reference)
#include <cuda_runtime.h>
#include <cstdint>
#include <cstddef>

#define BATCH 8
#define NPTS  4096
#define NS    1024
#define DIMF  32

// ----------------------------- static device scratch -----------------------------
__device__ float4 g_pxyz[BATCH * NPTS];          // x,y,z,|p|^2
__device__ float4 g_cent[BATCH * NS];            // centers x,y,z,|c|^2
__device__ int    g_idxAll[3 * BATCH * NS * 64]; // ball-query indices, stride 64
__device__ float  g_y1[67108864];                // up to 524288 x 128
__device__ float  g_y2[134217728];               // up to 524288 x 256
__device__ double g_sum[6][256];
__device__ double g_sq[6][256];
__device__ float  g_bnA[6][256];
__device__ float  g_bnB[6][256];

// ----------------------------- zero BN stats -----------------------------
__global__ void zero_kernel() {
    int t = threadIdx.x; // 256
    for (int s = 0; s < 6; s++) { g_sum[s][t] = 0.0; g_sq[s][t] = 0.0; }
}

// ----------------------------- pack xyz + |p|^2 -----------------------------
__global__ void pack_kernel(const float* __restrict__ xyz) {
    int i = blockIdx.x * 256 + threadIdx.x;
    if (i < BATCH * NPTS) {
        float x = xyz[3 * i], y = xyz[3 * i + 1], z = xyz[3 * i + 2];
        float nb = __fadd_rn(__fadd_rn(__fmul_rn(x, x), __fmul_rn(y, y)), __fmul_rn(z, z));
        g_pxyz[i] = make_float4(x, y, z, nb);
    }
}

// ----------------------------- farthest point sampling -----------------------------
// One block per batch; 512 threads x 8 points in registers.
// Rounding: rn mul/add, order (xx+yy)+zz, NO fma (match XLA). Tie-break: lowest index.
__global__ void __launch_bounds__(512) fps_kernel(const float* __restrict__ xyz) {
    const int b = blockIdx.x;
    const float* base = xyz + (size_t)b * NPTS * 3;
    const int t = threadIdx.x, lane = t & 31, warp = t >> 5;

    float px[8], py[8], pz[8], dist[8];
#pragma unroll
    for (int j = 0; j < 8; j++) {
        int p = t + j * 512;
        px[j] = base[3 * p]; py[j] = base[3 * p + 1]; pz[j] = base[3 * p + 2];
        dist[j] = 1e10f;
    }

    __shared__ float s_v[16];
    __shared__ int   s_i[16];
    __shared__ float s_x[2][16], s_y[2][16], s_z[2][16];
    __shared__ int   s_w;

    float cx = base[0], cy = base[1], cz = base[2]; // first center: index 0

    for (int it = 0; it < NS; it++) {
        const int pb = it & 1;
        if (t == 0) {
            float nrm = __fadd_rn(__fadd_rn(__fmul_rn(cx, cx), __fmul_rn(cy, cy)), __fmul_rn(cz, cz));
            g_cent[b * NS + it] = make_float4(cx, cy, cz, nrm);
        }
        float bv = -1.0f; int bi = 0x7fffffff;
#pragma unroll
        for (int j = 0; j < 8; j++) {
            float dx = __fsub_rn(px[j], cx);
            float dy = __fsub_rn(py[j], cy);
            float dz = __fsub_rn(pz[j], cz);
            float d  = __fadd_rn(__fadd_rn(__fmul_rn(dx, dx), __fmul_rn(dy, dy)), __fmul_rn(dz, dz));
            float nd = fminf(dist[j], d);
            dist[j] = nd;
            if (nd > bv) { bv = nd; bi = t + j * 512; } // ascending index scan -> strict >
        }
#pragma unroll
        for (int off = 16; off > 0; off >>= 1) {
            float ov = __shfl_xor_sync(0xffffffffu, bv, off);
            int   oi = __shfl_xor_sync(0xffffffffu, bi, off);
            if (ov > bv || (ov == bv && oi < bi)) { bv = ov; bi = oi; }
        }
        if ((bi & 31) == lane) {
            int j = bi >> 9;
            float ox = px[0], oy = py[0], oz = pz[0];
#pragma unroll
            for (int jj = 1; jj < 8; jj++)
                if (j == jj) { ox = px[jj]; oy = py[jj]; oz = pz[jj]; }
            s_v[warp] = bv; s_i[warp] = bi;
            s_x[pb][warp] = ox; s_y[pb][warp] = oy; s_z[pb][warp] = oz;
        }
        __syncthreads();
        if (warp == 0) {
            float v  = (lane < 16) ? s_v[lane] : -2.0f;
            int   i2 = (lane < 16) ? s_i[lane] : 0x7fffffff;
#pragma unroll
            for (int off = 8; off > 0; off >>= 1) {
                float ov = __shfl_xor_sync(0xffffffffu, v, off);
                int   oi = __shfl_xor_sync(0xffffffffu, i2, off);
                if (ov > v || (ov == v && oi < i2)) { v = ov; i2 = oi; }
            }
            if (lane == 0) s_w = (i2 & 511) >> 5;
        }
        __syncthreads();
        int w2 = s_w;
        cx = s_x[pb][w2]; cy = s_y[pb][w2]; cz = s_z[pb][w2];
    }
}

// copy new_xyz from g_cent into d_out (only when output layout includes it)
__global__ void copyxyz_kernel(float* __restrict__ out) {
    int i = blockIdx.x * 256 + threadIdx.x;
    if (i < BATCH * NS) {
        float4 c = g_cent[i];
        out[3 * i] = c.x; out[3 * i + 1] = c.y; out[3 * i + 2] = c.z;
    }
}

// ----------------------------- ball query (3 scales) -----------------------------
// grid (BATCH*NS/8, 3), block 256 = 8 warps; warp per center; index-ordered scan.
__global__ void __launch_bounds__(256) ballquery_kernel() {
    const int scale = blockIdx.y;
    const float r2 = (scale == 0) ? 0.01f : (scale == 1) ? 0.04f : 0.16f;
    const int K = 16 << scale;
    const int t = threadIdx.x, lane = t & 31, warp = t >> 5;
    const int g = blockIdx.x * 8 + warp;
    const int b = g >> 10;
    float4 c = g_cent[g];
    int* out = g_idxAll + scale * (BATCH * NS * 64) + g * 64;
    const float4* P = g_pxyz + ((size_t)b << 12);

    int cnt = 0, firstIdx = 0;
    for (int ch = 0; ch < NPTS / 32; ch++) {
        int p = (ch << 5) + lane;
        float4 q = P[p];
        float dot = __fadd_rn(__fadd_rn(__fmul_rn(c.x, q.x), __fmul_rn(c.y, q.y)), __fmul_rn(c.z, q.z));
        float d = __fsub_rn(__fadd_rn(c.w, q.w), __fadd_rn(dot, dot)); // (na+nb) - 2*dot
        bool ok = (d <= r2);
        unsigned mask = __ballot_sync(0xffffffffu, ok);
        if (mask) {
            if (cnt == 0) firstIdx = (ch << 5) + (__ffs(mask) - 1);
            if (ok) {
                int pos = cnt + __popc(mask & ((1u << lane) - 1u));
                if (pos < K) out[pos] = p;
            }
            cnt += __popc(mask);
            if (cnt >= K) break;
        }
    }
    if (cnt < K) {
        for (int i = cnt + lane; i < K; i += 32) out[i] = firstIdx;
    }
}

// ----------------------------- GEMM1: fused gather + feat@W1 + b1, BN stats -----------------------------
// 64-row x C1 tile per block, 256 threads, K-dim = 35 fully in smem.
template<int C1, int KLOG, int SCALE, int SLOT>
__global__ void __launch_bounds__(256) gemm1_kernel(const float* __restrict__ points,
                                                    const float* __restrict__ W,
                                                    const float* __restrict__ bias) {
    constexpr int KS = 1 << KLOG;
    constexpr int CT = C1 / 4;       // column-thread groups
    constexpr int RG = 256 / CT;     // row groups
    constexpr int RT = 64 / RG;      // rows per thread
    __shared__ float sA[64][36];
    __shared__ float sW[35][C1];
    __shared__ float sBias[C1];

    const int tid = threadIdx.x;
    const int r0 = blockIdx.x * 64;

    { // gather feat tile: thread = (row, quarter)
        int row = tid >> 2, sub = tid & 3;
        int gr = r0 + row;
        int b = gr >> (10 + KLOG);
        int s = (gr >> KLOG) & 1023;
        int k = gr & (KS - 1);
        int g = (b << 10) + s;
        int idx = g_idxAll[SCALE * (BATCH * NS * 64) + g * 64 + k];
        if (sub == 0) {
            float4 p = g_pxyz[(b << 12) + idx];
            float4 c = g_cent[g];
            sA[row][0] = p.x - c.x; sA[row][1] = p.y - c.y; sA[row][2] = p.z - c.z;
        }
        const float4* p4 = (const float4*)(points + ((((size_t)(b << 12)) + idx) << 5));
        float4 v0 = p4[sub * 2], v1 = p4[sub * 2 + 1];
        int cb = 3 + sub * 8;
        sA[row][cb + 0] = v0.x; sA[row][cb + 1] = v0.y; sA[row][cb + 2] = v0.z; sA[row][cb + 3] = v0.w;
        sA[row][cb + 4] = v1.x; sA[row][cb + 5] = v1.y; sA[row][cb + 6] = v1.z; sA[row][cb + 7] = v1.w;
    }
    for (int i = tid; i < 35 * C1; i += 256) sW[i / C1][i % C1] = W[i];
    if (tid < C1) sBias[tid] = bias[tid];
    __syncthreads();

    const int tx = tid % CT, ty = tid / CT;
    float acc[RT][4];
#pragma unroll
    for (int i = 0; i < RT; i++) { acc[i][0] = 0.f; acc[i][1] = 0.f; acc[i][2] = 0.f; acc[i][3] = 0.f; }

#pragma unroll
    for (int k = 0; k < 35; k++) {
        float4 w = *(const float4*)&sW[k][tx * 4];
#pragma unroll
        for (int i = 0; i < RT; i++) {
            float a = sA[ty * RT + i][k];
            acc[i][0] = fmaf(a, w.x, acc[i][0]);
            acc[i][1] = fmaf(a, w.y, acc[i][1]);
            acc[i][2] = fmaf(a, w.z, acc[i][2]);
            acc[i][3] = fmaf(a, w.w, acc[i][3]);
        }
    }

    float4 bb = *(const float4*)&sBias[tx * 4];
    float lsum[4] = {0.f, 0.f, 0.f, 0.f}, lsq[4] = {0.f, 0.f, 0.f, 0.f};
#pragma unroll
    for (int i = 0; i < RT; i++) {
        float4 v;
        v.x = acc[i][0] + bb.x; v.y = acc[i][1] + bb.y;
        v.z = acc[i][2] + bb.z; v.w = acc[i][3] + bb.w;
        *(float4*)&g_y1[((size_t)(r0 + ty * RT + i)) * C1 + tx * 4] = v;
        lsum[0] += v.x; lsq[0] += v.x * v.x;
        lsum[1] += v.y; lsq[1] += v.y * v.y;
        lsum[2] += v.z; lsq[2] += v.z * v.z;
        lsum[3] += v.w; lsq[3] += v.w * v.w;
    }
    __syncthreads();
    float* csum = &sA[0][0];
    float* csq  = csum + C1;
    if (tid < C1) { csum[tid] = 0.f; csq[tid] = 0.f; }
    __syncthreads();
#pragma unroll
    for (int j = 0; j < 4; j++) {
        atomicAdd(&csum[tx * 4 + j], lsum[j]);
        atomicAdd(&csq[tx * 4 + j], lsq[j]);
    }
    __syncthreads();
    if (tid < C1) {
        atomicAdd(&g_sum[SLOT][tid], (double)csum[tid]);
        atomicAdd(&g_sq[SLOT][tid],  (double)csq[tid]);
    }
}

// ----------------------------- BN finalize -----------------------------
__global__ void bnfin_kernel(int slot, int C, double invCount,
                             const float* __restrict__ gamma,
                             const float* __restrict__ beta) {
    int c = threadIdx.x;
    if (c < C) {
        double mean = g_sum[slot][c] * invCount;
        double var  = g_sq[slot][c] * invCount - mean * mean;
        float a = gamma[c] * rsqrtf((float)var + 1e-5f);
        g_bnA[slot][c] = a;
        g_bnB[slot][c] = beta[c] - (float)mean * a;
    }
}

// ----------------------------- GEMM2: relu(bn1(y1)) @ W2 + b2, BN stats -----------------------------
// 128x128 tile, BK=32, 256 threads, 8x8 microtile. BN1+ReLU fused into A-tile load.
template<int C1, int C2, int SLOT1, int SLOT2>
__global__ void __launch_bounds__(256) gemm2_kernel(const float* __restrict__ W2,
                                                    const float* __restrict__ bias2) {
    __shared__ float sA[128][36];
    __shared__ float sB[32][128];
    __shared__ float sBNa[C1], sBNb[C1], sBias[128];

    const int tid = threadIdx.x;
    const int r0 = blockIdx.x * 128;
    const int c0 = blockIdx.y * 128;

    for (int i = tid; i < C1; i += 256) { sBNa[i] = g_bnA[SLOT1][i]; sBNb[i] = g_bnB[SLOT1][i]; }
    if (tid < 128) sBias[tid] = bias2[c0 + tid];
    __syncthreads();

    const int tx = tid & 15, ty = tid >> 4;
    float acc[8][8];
#pragma unroll
    for (int i = 0; i < 8; i++)
#pragma unroll
        for (int j = 0; j < 8; j++) acc[i][j] = 0.f;

    for (int kc = 0; kc < C1; kc += 32) {
#pragma unroll
        for (int pass = 0; pass < 4; pass++) {
            int row = (tid >> 3) + pass * 32;
            int c4  = (tid & 7);
            float4 v = *(const float4*)&g_y1[((size_t)(r0 + row)) * C1 + kc + c4 * 4];
            int kb = kc + c4 * 4;
            v.x = fmaxf(fmaf(v.x, sBNa[kb + 0], sBNb[kb + 0]), 0.f);
            v.y = fmaxf(fmaf(v.y, sBNa[kb + 1], sBNb[kb + 1]), 0.f);
            v.z = fmaxf(fmaf(v.z, sBNa[kb + 2], sBNb[kb + 2]), 0.f);
            v.w = fmaxf(fmaf(v.w, sBNa[kb + 3], sBNb[kb + 3]), 0.f);
            *(float4*)&sA[row][c4 * 4] = v;
        }
#pragma unroll
        for (int j = 0; j < 4; j++) {
            int i4 = tid + j * 256;
            int br = i4 >> 5, bc = (i4 & 31) * 4;
            *(float4*)&sB[br][bc] = *(const float4*)&W2[(size_t)(kc + br) * C2 + c0 + bc];
        }
        __syncthreads();
#pragma unroll
        for (int kk = 0; kk < 32; kk++) {
            float4 b0 = *(const float4*)&sB[kk][tx * 8];
            float4 b1 = *(const float4*)&sB[kk][tx * 8 + 4];
            float a[8];
#pragma unroll
            for (int i = 0; i < 8; i++) a[i] = sA[ty * 8 + i][kk];
#pragma unroll
            for (int i = 0; i < 8; i++) {
                acc[i][0] = fmaf(a[i], b0.x, acc[i][0]);
                acc[i][1] = fmaf(a[i], b0.y, acc[i][1]);
                acc[i][2] = fmaf(a[i], b0.z, acc[i][2]);
                acc[i][3] = fmaf(a[i], b0.w, acc[i][3]);
                acc[i][4] = fmaf(a[i], b1.x, acc[i][4]);
                acc[i][5] = fmaf(a[i], b1.y, acc[i][5]);
                acc[i][6] = fmaf(a[i], b1.z, acc[i][6]);
                acc[i][7] = fmaf(a[i], b1.w, acc[i][7]);
            }
        }
        __syncthreads();
    }

    float4 bb0 = *(const float4*)&sBias[tx * 8];
    float4 bb1 = *(const float4*)&sBias[tx * 8 + 4];
    float lsum[8], lsq[8];
#pragma unroll
    for (int j = 0; j < 8; j++) { lsum[j] = 0.f; lsq[j] = 0.f; }
#pragma unroll
    for (int i = 0; i < 8; i++) {
        float4 v0, v1;
        v0.x = acc[i][0] + bb0.x; v0.y = acc[i][1] + bb0.y;
        v0.z = acc[i][2] + bb0.z; v0.w = acc[i][3] + bb0.w;
        v1.x = acc[i][4] + bb1.x; v1.y = acc[i][5] + bb1.y;
        v1.z = acc[i][6] + bb1.z; v1.w = acc[i][7] + bb1.w;
        size_t o = ((size_t)(r0 + ty * 8 + i)) * C2 + c0 + tx * 8;
        *(float4*)&g_y2[o] = v0;
        *(float4*)&g_y2[o + 4] = v1;
        lsum[0] += v0.x; lsq[0] += v0.x * v0.x;
        lsum[1] += v0.y; lsq[1] += v0.y * v0.y;
        lsum[2] += v0.z; lsq[2] += v0.z * v0.z;
        lsum[3] += v0.w; lsq[3] += v0.w * v0.w;
        lsum[4] += v1.x; lsq[4] += v1.x * v1.x;
        lsum[5] += v1.y; lsq[5] += v1.y * v1.y;
        lsum[6] += v1.z; lsq[6] += v1.z * v1.z;
        lsum[7] += v1.w; lsq[7] += v1.w * v1.w;
    }
    __syncthreads();
    float* csum = &sA[0][0];
    float* csq  = csum + 128;
    if (tid < 128) { csum[tid] = 0.f; csq[tid] = 0.f; }
    __syncthreads();
#pragma unroll
    for (int j = 0; j < 8; j++) {
        atomicAdd(&csum[tx * 8 + j], lsum[j]);
        atomicAdd(&csq[tx * 8 + j], lsq[j]);
    }
    __syncthreads();
    if (tid < 128) {
        atomicAdd(&g_sum[SLOT2][c0 + tid], (double)csum[tid]);
        atomicAdd(&g_sq[SLOT2][c0 + tid],  (double)csq[tid]);
    }
}

// ----------------------------- maxpool over K with BN2+ReLU, transposed write -----------------------------
template<int C2, int KS, int OFF, int SLOT>
__global__ void pool_kernel(float* __restrict__ outp) {
    int g = blockIdx.x;                     // b*NS + s
    int c = blockIdx.y * 128 + threadIdx.x; // channel within scale
    int b = g >> 10, s = g & 1023;
    float a = g_bnA[SLOT][c], sh = g_bnB[SLOT][c];
    const float* base = &g_y2[((size_t)g * KS) * C2 + c];
    float m = 0.f; // relu outputs are >= 0, so 0 is the exact identity
#pragma unroll 4
    for (int k = 0; k < KS; k++) {
        float v = base[(size_t)k * C2];
        m = fmaxf(m, fmaxf(fmaf(v, a, sh), 0.f));
    }
    outp[((size_t)b * 640 + OFF + c) * NS + s] = m;
}

// ----------------------------- launch -----------------------------
extern "C" void kernel_launch(void* const* d_in, const int* in_sizes, int n_in,
                              void* d_out, int out_size) {
    const float* xyz    = (const float*)d_in[0];
    const float* points = (const float*)d_in[1];
    const float* W[3][2]; const float* Bi[3][2]; const float* Ga[3][2]; const float* Be[3][2];
    for (int i = 0; i < 3; i++)
        for (int j = 0; j < 2; j++) {
            int base = 2 + i * 8 + j * 4;
            W[i][j]  = (const float*)d_in[base + 0];
            Bi[i][j] = (const float*)d_in[base + 1];
            Ga[i][j] = (const float*)d_in[base + 2];
            Be[i][j] = (const float*)d_in[base + 3];
        }

    float* out = (float*)d_out;
    const int XYZ_ELEMS = BATCH * NS * 3;        // 24576
    const int PTS_ELEMS = BATCH * 640 * NS;      // 5242880
    bool haveXyz = (out_size >= XYZ_ELEMS + PTS_ELEMS);
    float* outpts = out + (haveXyz ? XYZ_ELEMS : 0);

    zero_kernel<<<1, 256>>>();
    pack_kernel<<<(BATCH * NPTS + 255) / 256, 256>>>(xyz);
    fps_kernel<<<BATCH, 512>>>(xyz);
    if (haveXyz) copyxyz_kernel<<<(BATCH * NS + 255) / 256, 256>>>(out);
    ballquery_kernel<<<dim3(BATCH * NS / 8, 3), 256>>>();

    // scale 0: K=16, C1=64, C2=128, M=131072, ch offset 0
    gemm1_kernel<64, 4, 0, 0><<<131072 / 64, 256>>>(points, W[0][0], Bi[0][0]);
    bnfin_kernel<<<1, 256>>>(0, 64, 1.0 / 131072.0, Ga[0][0], Be[0][0]);
    gemm2_kernel<64, 128, 0, 1><<<dim3(131072 / 128, 1), 256>>>(W[0][1], Bi[0][1]);
    bnfin_kernel<<<1, 256>>>(1, 128, 1.0 / 131072.0, Ga[0][1], Be[0][1]);
    pool_kernel<128, 16, 0, 1><<<dim3(BATCH * NS, 1), 128>>>(outpts);

    // scale 1: K=32, C1=128, C2=256, M=262144, ch offset 128
    gemm1_kernel<128, 5, 1, 2><<<262144 / 64, 256>>>(points, W[1][0], Bi[1][0]);
    bnfin_kernel<<<1, 256>>>(2, 128, 1.0 / 262144.0, Ga[1][0], Be[1][0]);
    gemm2_kernel<128, 256, 2, 3><<<dim3(262144 / 128, 2), 256>>>(W[1][1], Bi[1][1]);
    bnfin_kernel<<<1, 256>>>(3, 256, 1.0 / 262144.0, Ga[1][1], Be[1][1]);
    pool_kernel<256, 32, 128, 3><<<dim3(BATCH * NS, 2), 128>>>(outpts);

    // scale 2: K=64, C1=128, C2=256, M=524288, ch offset 384
    gemm1_kernel<128, 6, 2, 4><<<524288 / 64, 256>>>(points, W[2][0], Bi[2][0]);
    bnfin_kernel<<<1, 256>>>(4, 128, 1.0 / 524288.0, Ga[2][0], Be[2][0]);
    gemm2_kernel<128, 256, 4, 5><<<dim3(524288 / 128, 2), 256>>>(W[2][1], Bi[2][1]);
    bnfin_kernel<<<1, 256>>>(5, 256, 1.0 / 524288.0, Ga[2][1], Be[2][1]);
    pool_kernel<256, 64, 384, 5><<<dim3(BATCH * NS, 2), 128>>>(outpts);
}

// round 3
// speedup vs baseline: 1.1781x; 1.1781x over previous
#include <cuda_runtime.h>
#include <cstdint>
#include <cstddef>

#define BATCH 8
#define NPTS  4096
#define NS    1024
#define DIMF  32

// ----------------------------- static device scratch -----------------------------
__device__ float4 g_pxyz[BATCH * NPTS];          // x,y,z,|p|^2
__device__ float4 g_cent[BATCH * NS];            // centers x,y,z,|c|^2
__device__ int    g_idxAll[3 * BATCH * NS * 64]; // ball-query indices, stride 64
__device__ float  g_y1[67108864];                // up to 524288 x 128
__device__ float  g_gmax[3][8192][256];          // per-scale group-max (pre-BN2)
__device__ double g_sum[6][256];
__device__ double g_sq[6][256];
__device__ float  g_bnA[6][256];
__device__ float  g_bnB[6][256];

// ----------------------------- zero BN stats -----------------------------
__global__ void zero_kernel() {
    int t = threadIdx.x; // 256
    for (int s = 0; s < 6; s++) { g_sum[s][t] = 0.0; g_sq[s][t] = 0.0; }
}

// ----------------------------- pack xyz + |p|^2 -----------------------------
__global__ void pack_kernel(const float* __restrict__ xyz) {
    int i = blockIdx.x * 256 + threadIdx.x;
    if (i < BATCH * NPTS) {
        float x = xyz[3 * i], y = xyz[3 * i + 1], z = xyz[3 * i + 2];
        float nb = __fadd_rn(__fadd_rn(__fmul_rn(x, x), __fmul_rn(y, y)), __fmul_rn(z, z));
        g_pxyz[i] = make_float4(x, y, z, nb);
    }
}

// ----------------------------- farthest point sampling (unchanged, passing) -----------------------------
__global__ void __launch_bounds__(512) fps_kernel(const float* __restrict__ xyz) {
    const int b = blockIdx.x;
    const float* base = xyz + (size_t)b * NPTS * 3;
    const int t = threadIdx.x, lane = t & 31, warp = t >> 5;

    float px[8], py[8], pz[8], dist[8];
#pragma unroll
    for (int j = 0; j < 8; j++) {
        int p = t + j * 512;
        px[j] = base[3 * p]; py[j] = base[3 * p + 1]; pz[j] = base[3 * p + 2];
        dist[j] = 1e10f;
    }

    __shared__ float s_v[16];
    __shared__ int   s_i[16];
    __shared__ float s_x[2][16], s_y[2][16], s_z[2][16];
    __shared__ int   s_w;

    float cx = base[0], cy = base[1], cz = base[2]; // first center: index 0

    for (int it = 0; it < NS; it++) {
        const int pb = it & 1;
        if (t == 0) {
            float nrm = __fadd_rn(__fadd_rn(__fmul_rn(cx, cx), __fmul_rn(cy, cy)), __fmul_rn(cz, cz));
            g_cent[b * NS + it] = make_float4(cx, cy, cz, nrm);
        }
        float bv = -1.0f; int bi = 0x7fffffff;
#pragma unroll
        for (int j = 0; j < 8; j++) {
            float dx = __fsub_rn(px[j], cx);
            float dy = __fsub_rn(py[j], cy);
            float dz = __fsub_rn(pz[j], cz);
            float d  = __fadd_rn(__fadd_rn(__fmul_rn(dx, dx), __fmul_rn(dy, dy)), __fmul_rn(dz, dz));
            float nd = fminf(dist[j], d);
            dist[j] = nd;
            if (nd > bv) { bv = nd; bi = t + j * 512; }
        }
#pragma unroll
        for (int off = 16; off > 0; off >>= 1) {
            float ov = __shfl_xor_sync(0xffffffffu, bv, off);
            int   oi = __shfl_xor_sync(0xffffffffu, bi, off);
            if (ov > bv || (ov == bv && oi < bi)) { bv = ov; bi = oi; }
        }
        if ((bi & 31) == lane) {
            int j = bi >> 9;
            float ox = px[0], oy = py[0], oz = pz[0];
#pragma unroll
            for (int jj = 1; jj < 8; jj++)
                if (j == jj) { ox = px[jj]; oy = py[jj]; oz = pz[jj]; }
            s_v[warp] = bv; s_i[warp] = bi;
            s_x[pb][warp] = ox; s_y[pb][warp] = oy; s_z[pb][warp] = oz;
        }
        __syncthreads();
        if (warp == 0) {
            float v  = (lane < 16) ? s_v[lane] : -2.0f;
            int   i2 = (lane < 16) ? s_i[lane] : 0x7fffffff;
#pragma unroll
            for (int off = 8; off > 0; off >>= 1) {
                float ov = __shfl_xor_sync(0xffffffffu, v, off);
                int   oi = __shfl_xor_sync(0xffffffffu, i2, off);
                if (ov > v || (ov == v && oi < i2)) { v = ov; i2 = oi; }
            }
            if (lane == 0) s_w = (i2 & 511) >> 5;
        }
        __syncthreads();
        int w2 = s_w;
        cx = s_x[pb][w2]; cy = s_y[pb][w2]; cz = s_z[pb][w2];
    }
}

// copy new_xyz from g_cent into d_out (only when output layout includes it)
__global__ void copyxyz_kernel(float* __restrict__ out) {
    int i = blockIdx.x * 256 + threadIdx.x;
    if (i < BATCH * NS) {
        float4 c = g_cent[i];
        out[3 * i] = c.x; out[3 * i + 1] = c.y; out[3 * i + 2] = c.z;
    }
}

// ----------------------------- ball query (3 scales, unchanged) -----------------------------
__global__ void __launch_bounds__(256) ballquery_kernel() {
    const int scale = blockIdx.y;
    const float r2 = (scale == 0) ? 0.01f : (scale == 1) ? 0.04f : 0.16f;
    const int K = 16 << scale;
    const int t = threadIdx.x, lane = t & 31, warp = t >> 5;
    const int g = blockIdx.x * 8 + warp;
    const int b = g >> 10;
    float4 c = g_cent[g];
    int* out = g_idxAll + scale * (BATCH * NS * 64) + g * 64;
    const float4* P = g_pxyz + ((size_t)b << 12);

    int cnt = 0, firstIdx = 0;
    for (int ch = 0; ch < NPTS / 32; ch++) {
        int p = (ch << 5) + lane;
        float4 q = P[p];
        float dot = __fadd_rn(__fadd_rn(__fmul_rn(c.x, q.x), __fmul_rn(c.y, q.y)), __fmul_rn(c.z, q.z));
        float d = __fsub_rn(__fadd_rn(c.w, q.w), __fadd_rn(dot, dot));
        bool ok = (d <= r2);
        unsigned mask = __ballot_sync(0xffffffffu, ok);
        if (mask) {
            if (cnt == 0) firstIdx = (ch << 5) + (__ffs(mask) - 1);
            if (ok) {
                int pos = cnt + __popc(mask & ((1u << lane) - 1u));
                if (pos < K) out[pos] = p;
            }
            cnt += __popc(mask);
            if (cnt >= K) break;
        }
    }
    if (cnt < K) {
        for (int i = cnt + lane; i < K; i += 32) out[i] = firstIdx;
    }
}

// ----------------------------- GEMM1: fused gather + feat@W1 + b1, BN stats (unchanged) -----------------------------
template<int C1, int KLOG, int SCALE, int SLOT>
__global__ void __launch_bounds__(256) gemm1_kernel(const float* __restrict__ points,
                                                    const float* __restrict__ W,
                                                    const float* __restrict__ bias) {
    constexpr int KS = 1 << KLOG;
    constexpr int CT = C1 / 4;
    constexpr int RG = 256 / CT;
    constexpr int RT = 64 / RG;
    __shared__ float sA[64][36];
    __shared__ float sW[35][C1];
    __shared__ float sBias[C1];

    const int tid = threadIdx.x;
    const int r0 = blockIdx.x * 64;

    {
        int row = tid >> 2, sub = tid & 3;
        int gr = r0 + row;
        int b = gr >> (10 + KLOG);
        int s = (gr >> KLOG) & 1023;
        int k = gr & (KS - 1);
        int g = (b << 10) + s;
        int idx = g_idxAll[SCALE * (BATCH * NS * 64) + g * 64 + k];
        if (sub == 0) {
            float4 p = g_pxyz[(b << 12) + idx];
            float4 c = g_cent[g];
            sA[row][0] = p.x - c.x; sA[row][1] = p.y - c.y; sA[row][2] = p.z - c.z;
        }
        const float4* p4 = (const float4*)(points + ((((size_t)(b << 12)) + idx) << 5));
        float4 v0 = p4[sub * 2], v1 = p4[sub * 2 + 1];
        int cb = 3 + sub * 8;
        sA[row][cb + 0] = v0.x; sA[row][cb + 1] = v0.y; sA[row][cb + 2] = v0.z; sA[row][cb + 3] = v0.w;
        sA[row][cb + 4] = v1.x; sA[row][cb + 5] = v1.y; sA[row][cb + 6] = v1.z; sA[row][cb + 7] = v1.w;
    }
    for (int i = tid; i < 35 * C1; i += 256) sW[i / C1][i % C1] = W[i];
    if (tid < C1) sBias[tid] = bias[tid];
    __syncthreads();

    const int tx = tid % CT, ty = tid / CT;
    float acc[RT][4];
#pragma unroll
    for (int i = 0; i < RT; i++) { acc[i][0] = 0.f; acc[i][1] = 0.f; acc[i][2] = 0.f; acc[i][3] = 0.f; }

#pragma unroll
    for (int k = 0; k < 35; k++) {
        float4 w = *(const float4*)&sW[k][tx * 4];
#pragma unroll
        for (int i = 0; i < RT; i++) {
            float a = sA[ty * RT + i][k];
            acc[i][0] = fmaf(a, w.x, acc[i][0]);
            acc[i][1] = fmaf(a, w.y, acc[i][1]);
            acc[i][2] = fmaf(a, w.z, acc[i][2]);
            acc[i][3] = fmaf(a, w.w, acc[i][3]);
        }
    }

    float4 bb = *(const float4*)&sBias[tx * 4];
    float lsum[4] = {0.f, 0.f, 0.f, 0.f}, lsq[4] = {0.f, 0.f, 0.f, 0.f};
#pragma unroll
    for (int i = 0; i < RT; i++) {
        float4 v;
        v.x = acc[i][0] + bb.x; v.y = acc[i][1] + bb.y;
        v.z = acc[i][2] + bb.z; v.w = acc[i][3] + bb.w;
        *(float4*)&g_y1[((size_t)(r0 + ty * RT + i)) * C1 + tx * 4] = v;
        lsum[0] += v.x; lsq[0] += v.x * v.x;
        lsum[1] += v.y; lsq[1] += v.y * v.y;
        lsum[2] += v.z; lsq[2] += v.z * v.z;
        lsum[3] += v.w; lsq[3] += v.w * v.w;
    }
    __syncthreads();
    float* csum = &sA[0][0];
    float* csq  = csum + C1;
    if (tid < C1) { csum[tid] = 0.f; csq[tid] = 0.f; }
    __syncthreads();
#pragma unroll
    for (int j = 0; j < 4; j++) {
        atomicAdd(&csum[tx * 4 + j], lsum[j]);
        atomicAdd(&csq[tx * 4 + j], lsq[j]);
    }
    __syncthreads();
    if (tid < C1) {
        atomicAdd(&g_sum[SLOT][tid], (double)csum[tid]);
        atomicAdd(&g_sq[SLOT][tid],  (double)csq[tid]);
    }
}

// ----------------------------- BN finalize -----------------------------
__global__ void bnfin_kernel(int slot, int C, double invCount,
                             const float* __restrict__ gamma,
                             const float* __restrict__ beta) {
    int c = threadIdx.x;
    if (c < C) {
        double mean = g_sum[slot][c] * invCount;
        double var  = g_sq[slot][c] * invCount - mean * mean;
        float a = gamma[c] * rsqrtf((float)var + 1e-5f);
        g_bnA[slot][c] = a;
        g_bnB[slot][c] = beta[c] - (float)mean * a;
    }
}

// ----------------------------- GEMM2: relu(bn1(y1)) @ W2 + b2, stats + fused K-group max -----------------------------
// 128x128 tile, BK=8, double-buffered, conflict-free smem. No y2 materialization:
// epilogue reduces max over K-sized row groups (BN2 is monotone: gamma==1 => a>0).
template<int C1, int C2, int KGRP, int SLOT1, int SLOT2, int SC>
__global__ void __launch_bounds__(256, 2) gemm2_kernel(const float* __restrict__ W2,
                                                       const float* __restrict__ bias2) {
    __shared__ float sA[2][8][132];    // k-major A (post BN1+ReLU)
    __shared__ float sB[2][8][128];
    __shared__ float sBNa[C1], sBNb[C1];
    __shared__ float sGmax[16][129];
    __shared__ float sStat[256];       // colsum[128] ++ colsq[128]

    const int tid = threadIdx.x;
    const int r0 = blockIdx.x * 128;
    const int c0 = blockIdx.y * 128;
    const int tx = tid & 15, ty = tid >> 4;

    for (int i = tid; i < C1; i += 256) { sBNa[i] = g_bnA[SLOT1][i]; sBNb[i] = g_bnB[SLOT1][i]; }
    __syncthreads();

    // loaders
    const int arow = tid >> 1, ak4 = tid & 1;          // A: 128 rows x 2 float4
    const int brow = tid >> 5, bcol = (tid & 31) * 4;  // B: 8 rows x 32 float4
    const float* Aptr = &g_y1[(size_t)(r0 + arow) * C1 + ak4 * 4];
    const float* Bptr = &W2[(size_t)brow * C2 + c0 + bcol];

    float4 av = *(const float4*)Aptr;
    float4 bv = *(const float4*)Bptr;

    // stage chunk 0 (apply BN1+ReLU to A)
    {
        int kb = ak4 * 4;
        float4 v;
        v.x = fmaxf(fmaf(av.x, sBNa[kb + 0], sBNb[kb + 0]), 0.f);
        v.y = fmaxf(fmaf(av.y, sBNa[kb + 1], sBNb[kb + 1]), 0.f);
        v.z = fmaxf(fmaf(av.z, sBNa[kb + 2], sBNb[kb + 2]), 0.f);
        v.w = fmaxf(fmaf(av.w, sBNa[kb + 3], sBNb[kb + 3]), 0.f);
        sA[0][ak4 * 4 + 0][arow] = v.x;
        sA[0][ak4 * 4 + 1][arow] = v.y;
        sA[0][ak4 * 4 + 2][arow] = v.z;
        sA[0][ak4 * 4 + 3][arow] = v.w;
        *(float4*)&sB[0][brow][bcol] = bv;
    }
    __syncthreads();

    float acc[8][8];
#pragma unroll
    for (int i = 0; i < 8; i++)
#pragma unroll
        for (int j = 0; j < 8; j++) acc[i][j] = 0.f;

    constexpr int NCH = C1 / 8;
    for (int kc = 0; kc < NCH; kc++) {
        const int cur = kc & 1, nxt = cur ^ 1;
        if (kc + 1 < NCH) {
            av = *(const float4*)(Aptr + (kc + 1) * 8);
            bv = *(const float4*)(Bptr + (size_t)(kc + 1) * 8 * C2);
        }
#pragma unroll
        for (int kk = 0; kk < 8; kk++) {
            float4 a0 = *(const float4*)&sA[cur][kk][ty * 8];
            float4 a1 = *(const float4*)&sA[cur][kk][ty * 8 + 4];
            float4 b0 = *(const float4*)&sB[cur][kk][tx * 4];
            float4 b1 = *(const float4*)&sB[cur][kk][64 + tx * 4];
            float ar[8] = {a0.x, a0.y, a0.z, a0.w, a1.x, a1.y, a1.z, a1.w};
#pragma unroll
            for (int i = 0; i < 8; i++) {
                acc[i][0] = fmaf(ar[i], b0.x, acc[i][0]);
                acc[i][1] = fmaf(ar[i], b0.y, acc[i][1]);
                acc[i][2] = fmaf(ar[i], b0.z, acc[i][2]);
                acc[i][3] = fmaf(ar[i], b0.w, acc[i][3]);
                acc[i][4] = fmaf(ar[i], b1.x, acc[i][4]);
                acc[i][5] = fmaf(ar[i], b1.y, acc[i][5]);
                acc[i][6] = fmaf(ar[i], b1.z, acc[i][6]);
                acc[i][7] = fmaf(ar[i], b1.w, acc[i][7]);
            }
        }
        if (kc + 1 < NCH) {
            int kb = (kc + 1) * 8 + ak4 * 4;
            float4 v;
            v.x = fmaxf(fmaf(av.x, sBNa[kb + 0], sBNb[kb + 0]), 0.f);
            v.y = fmaxf(fmaf(av.y, sBNa[kb + 1], sBNb[kb + 1]), 0.f);
            v.z = fmaxf(fmaf(av.z, sBNa[kb + 2], sBNb[kb + 2]), 0.f);
            v.w = fmaxf(fmaf(av.w, sBNa[kb + 3], sBNb[kb + 3]), 0.f);
            sA[nxt][ak4 * 4 + 0][arow] = v.x;
            sA[nxt][ak4 * 4 + 1][arow] = v.y;
            sA[nxt][ak4 * 4 + 2][arow] = v.z;
            sA[nxt][ak4 * 4 + 3][arow] = v.w;
            *(float4*)&sB[nxt][brow][bcol] = bv;
            __syncthreads();
        }
    }

    // ---- epilogue: bias, per-column sum/sumsq, per-(K-group, column) max ----
    float4 bb0 = *(const float4*)&bias2[c0 + tx * 4];
    float4 bb1 = *(const float4*)&bias2[c0 + 64 + tx * 4];
    float biasr[8] = {bb0.x, bb0.y, bb0.z, bb0.w, bb1.x, bb1.y, bb1.z, bb1.w};

    float lsum[8], lsq[8], lmax[8];
#pragma unroll
    for (int j = 0; j < 8; j++) { lsum[j] = 0.f; lsq[j] = 0.f; lmax[j] = -3.4e38f; }
#pragma unroll
    for (int i = 0; i < 8; i++) {
#pragma unroll
        for (int j = 0; j < 8; j++) {
            float v = acc[i][j] + biasr[j];
            lsum[j] += v; lsq[j] += v * v;
            lmax[j] = fmaxf(lmax[j], v);
        }
    }

    __syncthreads();  // done reading sA/sB? (separate arrays, but order stats init)
    if (tid < 256) sStat[tid] = 0.f;
#pragma unroll
    for (int j = 0; j < 8; j++) {
        int col = (j < 4) ? (tx * 4 + j) : (64 + tx * 4 + (j - 4));
        sGmax[ty][col] = lmax[j];
    }
    __syncthreads();
#pragma unroll
    for (int j = 0; j < 8; j++) {
        int col = (j < 4) ? (tx * 4 + j) : (64 + tx * 4 + (j - 4));
        atomicAdd(&sStat[col], lsum[j]);
        atomicAdd(&sStat[128 + col], lsq[j]);
    }
    // group-max reduce: 128/KGRP groups per tile, KGRP/8 ty-slots per group
    constexpr int GPB = 128 / KGRP;   // groups per block
    constexpr int TPG = KGRP / 8;     // ty entries per group
    for (int idx = tid; idx < GPB * 128; idx += 256) {
        int g = idx >> 7, c = idx & 127;
        float m = -3.4e38f;
#pragma unroll
        for (int t = 0; t < TPG; t++) m = fmaxf(m, sGmax[g * TPG + t][c]);
        g_gmax[SC][r0 / KGRP + g][c0 + c] = m;
    }
    __syncthreads();
    if (tid < 128) {
        atomicAdd(&g_sum[SLOT2][c0 + tid], (double)sStat[tid]);
        atomicAdd(&g_sq[SLOT2][c0 + tid],  (double)sStat[128 + tid]);
    }
}

// ----------------------------- final: relu(bn2(gmax)) + transposed write -----------------------------
template<int C2, int OFF, int SLOT, int SC>
__global__ void final_kernel(float* __restrict__ outp) {
    __shared__ float tile[32][33];
    const int tx = threadIdx.x, ty = threadIdx.y;   // (32, 8)
    const int g0 = blockIdx.x * 32, c0 = blockIdx.y * 32;
    float a  = g_bnA[SLOT][c0 + tx];
    float sh = g_bnB[SLOT][c0 + tx];
#pragma unroll
    for (int j = 0; j < 4; j++) {
        int row = g0 + ty + j * 8;
        float v = g_gmax[SC][row][c0 + tx];
        tile[ty + j * 8][tx] = fmaxf(fmaf(v, a, sh), 0.f);
    }
    __syncthreads();
    int b = (g0 + tx) >> 10, s = (g0 + tx) & 1023;
#pragma unroll
    for (int j = 0; j < 4; j++) {
        int c = c0 + ty + j * 8;
        outp[((size_t)b * 640 + OFF + c) * 1024 + s] = tile[tx][ty + j * 8];
    }
}

// ----------------------------- launch -----------------------------
extern "C" void kernel_launch(void* const* d_in, const int* in_sizes, int n_in,
                              void* d_out, int out_size) {
    const float* xyz    = (const float*)d_in[0];
    const float* points = (const float*)d_in[1];
    const float* W[3][2]; const float* Bi[3][2]; const float* Ga[3][2]; const float* Be[3][2];
    for (int i = 0; i < 3; i++)
        for (int j = 0; j < 2; j++) {
            int base = 2 + i * 8 + j * 4;
            W[i][j]  = (const float*)d_in[base + 0];
            Bi[i][j] = (const float*)d_in[base + 1];
            Ga[i][j] = (const float*)d_in[base + 2];
            Be[i][j] = (const float*)d_in[base + 3];
        }

    float* out = (float*)d_out;
    const int XYZ_ELEMS = BATCH * NS * 3;
    const int PTS_ELEMS = BATCH * 640 * NS;
    bool haveXyz = (out_size >= XYZ_ELEMS + PTS_ELEMS);
    float* outpts = out + (haveXyz ? XYZ_ELEMS : 0);

    zero_kernel<<<1, 256>>>();
    pack_kernel<<<(BATCH * NPTS + 255) / 256, 256>>>(xyz);
    fps_kernel<<<BATCH, 512>>>(xyz);
    if (haveXyz) copyxyz_kernel<<<(BATCH * NS + 255) / 256, 256>>>(out);
    ballquery_kernel<<<dim3(BATCH * NS / 8, 3), 256>>>();

    // scale 0: K=16, C1=64, C2=128, M=131072
    gemm1_kernel<64, 4, 0, 0><<<131072 / 64, 256>>>(points, W[0][0], Bi[0][0]);
    bnfin_kernel<<<1, 256>>>(0, 64, 1.0 / 131072.0, Ga[0][0], Be[0][0]);
    gemm2_kernel<64, 128, 16, 0, 1, 0><<<dim3(131072 / 128, 1), 256>>>(W[0][1], Bi[0][1]);
    bnfin_kernel<<<1, 256>>>(1, 128, 1.0 / 131072.0, Ga[0][1], Be[0][1]);
    final_kernel<128, 0, 1, 0><<<dim3(256, 4), dim3(32, 8)>>>(outpts);

    // scale 1: K=32, C1=128, C2=256, M=262144
    gemm1_kernel<128, 5, 1, 2><<<262144 / 64, 256>>>(points, W[1][0], Bi[1][0]);
    bnfin_kernel<<<1, 256>>>(2, 128, 1.0 / 262144.0, Ga[1][0], Be[1][0]);
    gemm2_kernel<128, 256, 32, 2, 3, 1><<<dim3(262144 / 128, 2), 256>>>(W[1][1], Bi[1][1]);
    bnfin_kernel<<<1, 256>>>(3, 256, 1.0 / 262144.0, Ga[1][1], Be[1][1]);
    final_kernel<256, 128, 3, 1><<<dim3(256, 8), dim3(32, 8)>>>(outpts);

    // scale 2: K=64, C1=128, C2=256, M=524288
    gemm1_kernel<128, 6, 2, 4><<<524288 / 64, 256>>>(points, W[2][0], Bi[2][0]);
    bnfin_kernel<<<1, 256>>>(4, 128, 1.0 / 524288.0, Ga[2][0], Be[2][0]);
    gemm2_kernel<128, 256, 64, 4, 5, 2><<<dim3(524288 / 128, 2), 256>>>(W[2][1], Bi[2][1]);
    bnfin_kernel<<<1, 256>>>(5, 256, 1.0 / 524288.0, Ga[2][1], Be[2][1]);
    final_kernel<256, 384, 5, 2><<<dim3(256, 8), dim3(32, 8)>>>(outpts);
}

// round 5
// speedup vs baseline: 1.4659x; 1.2443x over previous
#include <cuda_runtime.h>
#include <cuda_bf16.h>
#include <cstdint>
#include <cstddef>

#define BATCH 8
#define NPTS  4096
#define NS    1024
#define DIMF  32

// ----------------------------- static device scratch -----------------------------
__device__ float4 g_pxyz[BATCH * NPTS];          // x,y,z,|p|^2
__device__ float4 g_cent[BATCH * NS];            // centers x,y,z,|c|^2
__device__ int    g_idxAll[3 * BATCH * NS * 64]; // ball-query indices, stride 64
__device__ float  g_y1[67108864];                // up to 524288 x 128
__device__ float  g_gmax[3][8192][256];          // per-scale group-max (pre-BN2)
__device__ double g_sum[6][256];
__device__ double g_sq[6][256];
__device__ float  g_bnA[6][256];
__device__ float  g_bnB[6][256];
__device__ __align__(16) __nv_bfloat16 g_w2t_hi[3][32768]; // W2^T hi split [n*K+k]
__device__ __align__(16) __nv_bfloat16 g_w2t_lo[3][32768]; // W2^T lo split

__device__ __forceinline__ uint32_t smem_u32(const void* p) {
    uint32_t a;
    asm("{ .reg .u64 t; cvta.to.shared.u64 t, %1; cvt.u32.u64 %0, t; }" : "=r"(a) : "l"(p));
    return a;
}

// ----------------------------- zero BN stats -----------------------------
__global__ void zero_kernel() {
    int t = threadIdx.x; // 256
    for (int s = 0; s < 6; s++) { g_sum[s][t] = 0.0; g_sq[s][t] = 0.0; }
}

// ----------------------------- W2 transpose + bf16 split prep -----------------------------
__global__ void w2prep_kernel(const float* __restrict__ W2, int K, int C2, int sc) {
    int idx = blockIdx.x * 256 + threadIdx.x;
    if (idx < K * C2) {
        int n = idx / K, k = idx % K;
        float v = W2[(size_t)k * C2 + n];
        __nv_bfloat16 h = __float2bfloat16_rn(v);
        float lo = v - __bfloat162float(h);
        g_w2t_hi[sc][idx] = h;
        g_w2t_lo[sc][idx] = __float2bfloat16_rn(lo);
    }
}

// ----------------------------- pack xyz + |p|^2 -----------------------------
__global__ void pack_kernel(const float* __restrict__ xyz) {
    int i = blockIdx.x * 256 + threadIdx.x;
    if (i < BATCH * NPTS) {
        float x = xyz[3 * i], y = xyz[3 * i + 1], z = xyz[3 * i + 2];
        float nb = __fadd_rn(__fadd_rn(__fmul_rn(x, x), __fmul_rn(y, y)), __fmul_rn(z, z));
        g_pxyz[i] = make_float4(x, y, z, nb);
    }
}

// ----------------------------- farthest point sampling (unchanged, passing) -----------------------------
__global__ void __launch_bounds__(512) fps_kernel(const float* __restrict__ xyz) {
    const int b = blockIdx.x;
    const float* base = xyz + (size_t)b * NPTS * 3;
    const int t = threadIdx.x, lane = t & 31, warp = t >> 5;

    float px[8], py[8], pz[8], dist[8];
#pragma unroll
    for (int j = 0; j < 8; j++) {
        int p = t + j * 512;
        px[j] = base[3 * p]; py[j] = base[3 * p + 1]; pz[j] = base[3 * p + 2];
        dist[j] = 1e10f;
    }

    __shared__ float s_v[16];
    __shared__ int   s_i[16];
    __shared__ float s_x[2][16], s_y[2][16], s_z[2][16];
    __shared__ int   s_w;

    float cx = base[0], cy = base[1], cz = base[2];

    for (int it = 0; it < NS; it++) {
        const int pb = it & 1;
        if (t == 0) {
            float nrm = __fadd_rn(__fadd_rn(__fmul_rn(cx, cx), __fmul_rn(cy, cy)), __fmul_rn(cz, cz));
            g_cent[b * NS + it] = make_float4(cx, cy, cz, nrm);
        }
        float bv = -1.0f; int bi = 0x7fffffff;
#pragma unroll
        for (int j = 0; j < 8; j++) {
            float dx = __fsub_rn(px[j], cx);
            float dy = __fsub_rn(py[j], cy);
            float dz = __fsub_rn(pz[j], cz);
            float d  = __fadd_rn(__fadd_rn(__fmul_rn(dx, dx), __fmul_rn(dy, dy)), __fmul_rn(dz, dz));
            float nd = fminf(dist[j], d);
            dist[j] = nd;
            if (nd > bv) { bv = nd; bi = t + j * 512; }
        }
#pragma unroll
        for (int off = 16; off > 0; off >>= 1) {
            float ov = __shfl_xor_sync(0xffffffffu, bv, off);
            int   oi = __shfl_xor_sync(0xffffffffu, bi, off);
            if (ov > bv || (ov == bv && oi < bi)) { bv = ov; bi = oi; }
        }
        if ((bi & 31) == lane) {
            int j = bi >> 9;
            float ox = px[0], oy = py[0], oz = pz[0];
#pragma unroll
            for (int jj = 1; jj < 8; jj++)
                if (j == jj) { ox = px[jj]; oy = py[jj]; oz = pz[jj]; }
            s_v[warp] = bv; s_i[warp] = bi;
            s_x[pb][warp] = ox; s_y[pb][warp] = oy; s_z[pb][warp] = oz;
        }
        __syncthreads();
        if (warp == 0) {
            float v  = (lane < 16) ? s_v[lane] : -2.0f;
            int   i2 = (lane < 16) ? s_i[lane] : 0x7fffffff;
#pragma unroll
            for (int off = 8; off > 0; off >>= 1) {
                float ov = __shfl_xor_sync(0xffffffffu, v, off);
                int   oi = __shfl_xor_sync(0xffffffffu, i2, off);
                if (ov > v || (ov == v && oi < i2)) { v = ov; i2 = oi; }
            }
            if (lane == 0) s_w = (i2 & 511) >> 5;
        }
        __syncthreads();
        int w2 = s_w;
        cx = s_x[pb][w2]; cy = s_y[pb][w2]; cz = s_z[pb][w2];
    }
}

// copy new_xyz from g_cent into d_out
__global__ void copyxyz_kernel(float* __restrict__ out) {
    int i = blockIdx.x * 256 + threadIdx.x;
    if (i < BATCH * NS) {
        float4 c = g_cent[i];
        out[3 * i] = c.x; out[3 * i + 1] = c.y; out[3 * i + 2] = c.z;
    }
}

// ----------------------------- ball query (3 scales, unchanged) -----------------------------
__global__ void __launch_bounds__(256) ballquery_kernel() {
    const int scale = blockIdx.y;
    const float r2 = (scale == 0) ? 0.01f : (scale == 1) ? 0.04f : 0.16f;
    const int K = 16 << scale;
    const int t = threadIdx.x, lane = t & 31, warp = t >> 5;
    const int g = blockIdx.x * 8 + warp;
    const int b = g >> 10;
    float4 c = g_cent[g];
    int* out = g_idxAll + scale * (BATCH * NS * 64) + g * 64;
    const float4* P = g_pxyz + ((size_t)b << 12);

    int cnt = 0, firstIdx = 0;
    for (int ch = 0; ch < NPTS / 32; ch++) {
        int p = (ch << 5) + lane;
        float4 q = P[p];
        float dot = __fadd_rn(__fadd_rn(__fmul_rn(c.x, q.x), __fmul_rn(c.y, q.y)), __fmul_rn(c.z, q.z));
        float d = __fsub_rn(__fadd_rn(c.w, q.w), __fadd_rn(dot, dot));
        bool ok = (d <= r2);
        unsigned mask = __ballot_sync(0xffffffffu, ok);
        if (mask) {
            if (cnt == 0) firstIdx = (ch << 5) + (__ffs(mask) - 1);
            if (ok) {
                int pos = cnt + __popc(mask & ((1u << lane) - 1u));
                if (pos < K) out[pos] = p;
            }
            cnt += __popc(mask);
            if (cnt >= K) break;
        }
    }
    if (cnt < K) {
        for (int i = cnt + lane; i < K; i += 32) out[i] = firstIdx;
    }
}

// ----------------------------- GEMM1: fused gather + feat@W1 + b1, BN stats (unchanged) -----------------------------
template<int C1, int KLOG, int SCALE, int SLOT>
__global__ void __launch_bounds__(256) gemm1_kernel(const float* __restrict__ points,
                                                    const float* __restrict__ W,
                                                    const float* __restrict__ bias) {
    constexpr int KS = 1 << KLOG;
    constexpr int CT = C1 / 4;
    constexpr int RG = 256 / CT;
    constexpr int RT = 64 / RG;
    __shared__ float sA[64][36];
    __shared__ float sW[35][C1];
    __shared__ float sBias[C1];

    const int tid = threadIdx.x;
    const int r0 = blockIdx.x * 64;

    {
        int row = tid >> 2, sub = tid & 3;
        int gr = r0 + row;
        int b = gr >> (10 + KLOG);
        int s = (gr >> KLOG) & 1023;
        int k = gr & (KS - 1);
        int g = (b << 10) + s;
        int idx = g_idxAll[SCALE * (BATCH * NS * 64) + g * 64 + k];
        if (sub == 0) {
            float4 p = g_pxyz[(b << 12) + idx];
            float4 c = g_cent[g];
            sA[row][0] = p.x - c.x; sA[row][1] = p.y - c.y; sA[row][2] = p.z - c.z;
        }
        const float4* p4 = (const float4*)(points + ((((size_t)(b << 12)) + idx) << 5));
        float4 v0 = p4[sub * 2], v1 = p4[sub * 2 + 1];
        int cb = 3 + sub * 8;
        sA[row][cb + 0] = v0.x; sA[row][cb + 1] = v0.y; sA[row][cb + 2] = v0.z; sA[row][cb + 3] = v0.w;
        sA[row][cb + 4] = v1.x; sA[row][cb + 5] = v1.y; sA[row][cb + 6] = v1.z; sA[row][cb + 7] = v1.w;
    }
    for (int i = tid; i < 35 * C1; i += 256) sW[i / C1][i % C1] = W[i];
    if (tid < C1) sBias[tid] = bias[tid];
    __syncthreads();

    const int tx = tid % CT, ty = tid / CT;
    float acc[RT][4];
#pragma unroll
    for (int i = 0; i < RT; i++) { acc[i][0] = 0.f; acc[i][1] = 0.f; acc[i][2] = 0.f; acc[i][3] = 0.f; }

#pragma unroll
    for (int k = 0; k < 35; k++) {
        float4 w = *(const float4*)&sW[k][tx * 4];
#pragma unroll
        for (int i = 0; i < RT; i++) {
            float a = sA[ty * RT + i][k];
            acc[i][0] = fmaf(a, w.x, acc[i][0]);
            acc[i][1] = fmaf(a, w.y, acc[i][1]);
            acc[i][2] = fmaf(a, w.z, acc[i][2]);
            acc[i][3] = fmaf(a, w.w, acc[i][3]);
        }
    }

    float4 bb = *(const float4*)&sBias[tx * 4];
    float lsum[4] = {0.f, 0.f, 0.f, 0.f}, lsq[4] = {0.f, 0.f, 0.f, 0.f};
#pragma unroll
    for (int i = 0; i < RT; i++) {
        float4 v;
        v.x = acc[i][0] + bb.x; v.y = acc[i][1] + bb.y;
        v.z = acc[i][2] + bb.z; v.w = acc[i][3] + bb.w;
        *(float4*)&g_y1[((size_t)(r0 + ty * RT + i)) * C1 + tx * 4] = v;
        lsum[0] += v.x; lsq[0] += v.x * v.x;
        lsum[1] += v.y; lsq[1] += v.y * v.y;
        lsum[2] += v.z; lsq[2] += v.z * v.z;
        lsum[3] += v.w; lsq[3] += v.w * v.w;
    }
    __syncthreads();
    float* csum = &sA[0][0];
    float* csq  = csum + C1;
    if (tid < C1) { csum[tid] = 0.f; csq[tid] = 0.f; }
    __syncthreads();
#pragma unroll
    for (int j = 0; j < 4; j++) {
        atomicAdd(&csum[tx * 4 + j], lsum[j]);
        atomicAdd(&csq[tx * 4 + j], lsq[j]);
    }
    __syncthreads();
    if (tid < C1) {
        atomicAdd(&g_sum[SLOT][tid], (double)csum[tid]);
        atomicAdd(&g_sq[SLOT][tid],  (double)csq[tid]);
    }
}

// ----------------------------- BN finalize -----------------------------
__global__ void bnfin_kernel(int slot, int C, double invCount,
                             const float* __restrict__ gamma,
                             const float* __restrict__ beta) {
    int c = threadIdx.x;
    if (c < C) {
        double mean = g_sum[slot][c] * invCount;
        double var  = g_sq[slot][c] * invCount - mean * mean;
        float a = gamma[c] * rsqrtf((float)var + 1e-5f);
        g_bnA[slot][c] = a;
        g_bnB[slot][c] = beta[c] - (float)mean * a;
    }
}

// ----------------------------- GEMM2 via mma.sync bf16x3 (fp32 accum) -----------------------------
// 128(M)x128(N) tile per CTA, whole K in smem: A_hi/A_lo (BN1+ReLU+split of y1),
// B_hi/B_lo (pre-split W2^T). 3 passes: hi*hi + lo*hi + hi*lo.
// Epilogue: bias + col sum/sumsq + fused K-group maxpool.
__device__ __forceinline__ void mma_bf16(float* c, const uint32_t* a, const uint32_t* b) {
    asm volatile("mma.sync.aligned.m16n8k16.row.col.f32.bf16.bf16.f32 "
                 "{%0,%1,%2,%3}, {%4,%5,%6,%7}, {%8,%9}, {%0,%1,%2,%3};"
                 : "+f"(c[0]), "+f"(c[1]), "+f"(c[2]), "+f"(c[3])
                 : "r"(a[0]), "r"(a[1]), "r"(a[2]), "r"(a[3]), "r"(b[0]), "r"(b[1]));
}
__device__ __forceinline__ void ldsm4(uint32_t* r, uint32_t addr) {
    asm volatile("ldmatrix.sync.aligned.m8n8.x4.shared.b16 {%0,%1,%2,%3}, [%4];"
                 : "=r"(r[0]), "=r"(r[1]), "=r"(r[2]), "=r"(r[3]) : "r"(addr));
}

template<int K, int KGRP, int SLOT1, int SLOT2, int SC>
__global__ void __launch_bounds__(256) gemm2_mma(const float* __restrict__ bias2) {
    extern __shared__ char smem[];
    constexpr int TILE = 128 * K * 2;   // bytes per bf16 tile
    constexpr int RU = K / 8;           // 16B units per row
    char* A_HI = smem;
    char* A_LO = smem + TILE;
    char* B_HI = smem + 2 * TILE;
    char* B_LO = smem + 3 * TILE;
    float* sEpi = (float*)smem;         // [128][132], aliases tiles post-MMA

    __shared__ float sBias[128];
    __shared__ float sG[8][128];
    __shared__ float sSum[128];
    __shared__ float sSq[128];

    const int tid = threadIdx.x;
    const int wid = tid >> 5, lane = tid & 31;
    const int r0 = blockIdx.x * 128;
    const int c0 = blockIdx.y * 128;

    if (tid < 128) { sBias[tid] = bias2[c0 + tid]; sSum[tid] = 0.f; sSq[tid] = 0.f; }

    // ---- stage A (BN1+ReLU+split) and B (pre-split) into swizzled smem ----
    union Pack { __nv_bfloat16 h[8]; uint4 u; };
#pragma unroll
    for (int i = 0; i < 128 * RU / 256; i++) {
        int idx = tid + i * 256;
        int row = idx / RU, ku = idx % RU;
        int k = ku * 8;
        uint32_t off = (uint32_t)row * (K * 2) + (((ku & ~7) | ((ku ^ (row & 7)) & 7)) << 4);
        // A
        float4 v0 = *(const float4*)&g_y1[(size_t)(r0 + row) * K + k];
        float4 v1 = *(const float4*)&g_y1[(size_t)(r0 + row) * K + k + 4];
        float f[8] = {v0.x, v0.y, v0.z, v0.w, v1.x, v1.y, v1.z, v1.w};
        Pack ph, pl;
#pragma unroll
        for (int j = 0; j < 8; j++) {
            float v = fmaxf(fmaf(f[j], g_bnA[SLOT1][k + j], g_bnB[SLOT1][k + j]), 0.f);
            __nv_bfloat16 h = __float2bfloat16_rn(v);
            ph.h[j] = h;
            pl.h[j] = __float2bfloat16_rn(v - __bfloat162float(h));
        }
        *(uint4*)(A_HI + off) = ph.u;
        *(uint4*)(A_LO + off) = pl.u;
        // B
        *(uint4*)(B_HI + off) = *(const uint4*)&g_w2t_hi[SC][(size_t)(c0 + row) * K + k];
        *(uint4*)(B_LO + off) = *(const uint4*)&g_w2t_lo[SC][(size_t)(c0 + row) * K + k];
    }
    __syncthreads();

    // ---- warp tiling: 2(M) x 4(N) warps, 64x32 per warp ----
    const int wm = wid >> 2, wn = wid & 3;
    const int m_base = wm * 64, n_base = wn * 32;
    const uint32_t sbase = smem_u32(smem);
    const int mat = lane >> 3, r8 = lane & 7;

    // per-thread fixed row components
    int a_row[4], b_row[2];
    int a_ke = mat >> 1;            // A k-unit extra
    int b_ke = mat & 1;             // B k-unit extra
#pragma unroll
    for (int f = 0; f < 4; f++) a_row[f] = m_base + f * 16 + (mat & 1) * 8 + r8;
#pragma unroll
    for (int j = 0; j < 2; j++) b_row[j] = n_base + 16 * j + (mat >> 1) * 8 + r8;

    float acc[4][4][4];
#pragma unroll
    for (int mf = 0; mf < 4; mf++)
#pragma unroll
        for (int nf = 0; nf < 4; nf++)
#pragma unroll
            for (int q = 0; q < 4; q++) acc[mf][nf][q] = 0.f;

#pragma unroll 1
    for (int t = 0; t < 3; t++) {
        uint32_t Ab = sbase + ((t == 1) ? TILE : 0);
        uint32_t Bb = sbase + ((t == 2) ? 3 * TILE : 2 * TILE);
#pragma unroll
        for (int k = 0; k < K; k += 16) {
            int ku0 = k >> 3;
            uint32_t a[4][4], b[2][4];
#pragma unroll
            for (int f = 0; f < 4; f++) {
                int ku = ku0 + a_ke;
                uint32_t pu = (ku & ~7) | ((ku ^ (a_row[f] & 7)) & 7);
                ldsm4(a[f], Ab + (uint32_t)a_row[f] * (K * 2) + (pu << 4));
            }
#pragma unroll
            for (int j = 0; j < 2; j++) {
                int ku = ku0 + b_ke;
                uint32_t pu = (ku & ~7) | ((ku ^ (b_row[j] & 7)) & 7);
                ldsm4(b[j], Bb + (uint32_t)b_row[j] * (K * 2) + (pu << 4));
            }
#pragma unroll
            for (int mf = 0; mf < 4; mf++) {
#pragma unroll
                for (int nf = 0; nf < 4; nf++) {
                    // b frag for nf: pair j = nf>>1, regs {0,1} or {2,3}
                    uint32_t bfrag[2] = { b[nf >> 1][(nf & 1) * 2], b[nf >> 1][(nf & 1) * 2 + 1] };
                    mma_bf16(acc[mf][nf], a[mf], bfrag);
                }
            }
        }
    }
    __syncthreads();   // tiles dead; reuse smem as sEpi

    // ---- write acc + bias to sEpi ----
#pragma unroll
    for (int mf = 0; mf < 4; mf++) {
#pragma unroll
        for (int nf = 0; nf < 4; nf++) {
            int row = m_base + mf * 16 + (lane >> 2);
            int col = n_base + nf * 8 + (lane & 3) * 2;
            float2 v0 = make_float2(acc[mf][nf][0] + sBias[col], acc[mf][nf][1] + sBias[col + 1]);
            float2 v1 = make_float2(acc[mf][nf][2] + sBias[col], acc[mf][nf][3] + sBias[col + 1]);
            *(float2*)&sEpi[(size_t)row * 132 + col] = v0;
            *(float2*)&sEpi[(size_t)(row + 8) * 132 + col] = v1;
        }
    }
    __syncthreads();

    // ---- per-warp 16-row stats over all 128 cols ----
    for (int c = lane; c < 128; c += 32) {
        float sum = 0.f, sq = 0.f, mx = -3.4e38f;
#pragma unroll
        for (int r = 0; r < 16; r++) {
            float v = sEpi[(size_t)(wid * 16 + r) * 132 + c];
            sum += v; sq += v * v; mx = fmaxf(mx, v);
        }
        sG[wid][c] = mx;
        atomicAdd(&sSum[c], sum);
        atomicAdd(&sSq[c], sq);
    }
    __syncthreads();

    // ---- merges ----
    constexpr int GPB = 128 / KGRP;   // groups per tile
    constexpr int TPG = KGRP / 16;    // 16-row subs per group
    for (int idx = tid; idx < GPB * 128; idx += 256) {
        int g = idx >> 7, c = idx & 127;
        float m = -3.4e38f;
#pragma unroll
        for (int t = 0; t < TPG; t++) m = fmaxf(m, sG[g * TPG + t][c]);
        g_gmax[SC][r0 / KGRP + g][c0 + c] = m;
    }
    if (tid < 128) {
        atomicAdd(&g_sum[SLOT2][c0 + tid], (double)sSum[tid]);
        atomicAdd(&g_sq[SLOT2][c0 + tid],  (double)sSq[tid]);
    }
}

// ----------------------------- final: relu(bn2(gmax)) + transposed write -----------------------------
template<int C2, int OFF, int SLOT, int SC>
__global__ void final_kernel(float* __restrict__ outp) {
    __shared__ float tile[32][33];
    const int tx = threadIdx.x, ty = threadIdx.y;   // (32, 8)
    const int g0 = blockIdx.x * 32, c0 = blockIdx.y * 32;
    float a  = g_bnA[SLOT][c0 + tx];
    float sh = g_bnB[SLOT][c0 + tx];
#pragma unroll
    for (int j = 0; j < 4; j++) {
        int row = g0 + ty + j * 8;
        float v = g_gmax[SC][row][c0 + tx];
        tile[ty + j * 8][tx] = fmaxf(fmaf(v, a, sh), 0.f);
    }
    __syncthreads();
    int b = (g0 + tx) >> 10, s = (g0 + tx) & 1023;
#pragma unroll
    for (int j = 0; j < 4; j++) {
        int c = c0 + ty + j * 8;
        outp[((size_t)b * 640 + OFF + c) * 1024 + s] = tile[tx][ty + j * 8];
    }
}

// ----------------------------- launch -----------------------------
extern "C" void kernel_launch(void* const* d_in, const int* in_sizes, int n_in,
                              void* d_out, int out_size) {
    const float* xyz    = (const float*)d_in[0];
    const float* points = (const float*)d_in[1];
    const float* W[3][2]; const float* Bi[3][2]; const float* Ga[3][2]; const float* Be[3][2];
    for (int i = 0; i < 3; i++)
        for (int j = 0; j < 2; j++) {
            int base = 2 + i * 8 + j * 4;
            W[i][j]  = (const float*)d_in[base + 0];
            Bi[i][j] = (const float*)d_in[base + 1];
            Ga[i][j] = (const float*)d_in[base + 2];
            Be[i][j] = (const float*)d_in[base + 3];
        }

    float* out = (float*)d_out;
    const int XYZ_ELEMS = BATCH * NS * 3;
    const int PTS_ELEMS = BATCH * 640 * NS;
    bool haveXyz = (out_size >= XYZ_ELEMS + PTS_ELEMS);
    float* outpts = out + (haveXyz ? XYZ_ELEMS : 0);

    // dynamic smem: max(4 bf16 tiles, epi staging 128*132*4 = 67584)
    const int EPI = 128 * 132 * 4;
    const int SM0 = (4 * 128 * 64 * 2 > EPI) ? 4 * 128 * 64 * 2 : EPI;    // K=64  -> 67584
    const int SM1 = (4 * 128 * 128 * 2 > EPI) ? 4 * 128 * 128 * 2 : EPI;  // K=128 -> 131072
    cudaFuncSetAttribute(gemm2_mma<64, 16, 0, 1, 0>,  cudaFuncAttributeMaxDynamicSharedMemorySize, SM0);
    cudaFuncSetAttribute(gemm2_mma<128, 32, 2, 3, 1>, cudaFuncAttributeMaxDynamicSharedMemorySize, SM1);
    cudaFuncSetAttribute(gemm2_mma<128, 64, 4, 5, 2>, cudaFuncAttributeMaxDynamicSharedMemorySize, SM1);

    zero_kernel<<<1, 256>>>();
    w2prep_kernel<<<(64 * 128 + 255) / 256, 256>>>(W[0][1], 64, 128, 0);
    w2prep_kernel<<<(128 * 256 + 255) / 256, 256>>>(W[1][1], 128, 256, 1);
    w2prep_kernel<<<(128 * 256 + 255) / 256, 256>>>(W[2][1], 128, 256, 2);
    pack_kernel<<<(BATCH * NPTS + 255) / 256, 256>>>(xyz);
    fps_kernel<<<BATCH, 512>>>(xyz);
    if (haveXyz) copyxyz_kernel<<<(BATCH * NS + 255) / 256, 256>>>(out);
    ballquery_kernel<<<dim3(BATCH * NS / 8, 3), 256>>>();

    // scale 0: Ksamp=16, C1=64, C2=128, M=131072
    gemm1_kernel<64, 4, 0, 0><<<131072 / 64, 256>>>(points, W[0][0], Bi[0][0]);
    bnfin_kernel<<<1, 256>>>(0, 64, 1.0 / 131072.0, Ga[0][0], Be[0][0]);
    gemm2_mma<64, 16, 0, 1, 0><<<dim3(131072 / 128, 1), 256, SM0>>>(Bi[0][1]);
    bnfin_kernel<<<1, 256>>>(1, 128, 1.0 / 131072.0, Ga[0][1], Be[0][1]);
    final_kernel<128, 0, 1, 0><<<dim3(256, 4), dim3(32, 8)>>>(outpts);

    // scale 1: Ksamp=32, C1=128, C2=256, M=262144
    gemm1_kernel<128, 5, 1, 2><<<262144 / 64, 256>>>(points, W[1][0], Bi[1][0]);
    bnfin_kernel<<<1, 256>>>(2, 128, 1.0 / 262144.0, Ga[1][0], Be[1][0]);
    gemm2_mma<128, 32, 2, 3, 1><<<dim3(262144 / 128, 2), 256, SM1>>>(Bi[1][1]);
    bnfin_kernel<<<1, 256>>>(3, 256, 1.0 / 262144.0, Ga[1][1], Be[1][1]);
    final_kernel<256, 128, 3, 1><<<dim3(256, 8), dim3(32, 8)>>>(outpts);

    // scale 2: Ksamp=64, C1=128, C2=256, M=524288
    gemm1_kernel<128, 6, 2, 4><<<524288 / 64, 256>>>(points, W[2][0], Bi[2][0]);
    bnfin_kernel<<<1, 256>>>(4, 128, 1.0 / 524288.0, Ga[2][0], Be[2][0]);
    gemm2_mma<128, 64, 4, 5, 2><<<dim3(524288 / 128, 2), 256, SM1>>>(Bi[2][1]);
    bnfin_kernel<<<1, 256>>>(5, 256, 1.0 / 524288.0, Ga[2][1], Be[2][1]);
    final_kernel<256, 384, 5, 2><<<dim3(256, 8), dim3(32, 8)>>>(outpts);
}